// round 15
// baseline (speedup 1.0000x reference)
#include <cuda_runtime.h>
#include <cstdint>

#define NE 2000
#define NB 8
#define NHID 256
#define ALPHA 0.2f
#define MASKF 9e-15f
#define L2E 1.4426950408889634f
#define KM (NE * 3)          // 6000
#define NCTA 148
#define NTHR 1024
#define WPB 32
#define ROWS_TOTAL (NB * NE) // 16000 rows of 8KB, fully linear in adj
#define RING 16
#define ROW_BYTES 8000
#define CONS_W 16            // consumer warps 0..15; warp w owns ring slot w (SPSC)

// Device scratch (no allocations allowed)
__device__ float g_s2[NE];
__device__ float g_h0[NE];
__device__ float g_h1[NE];
__device__ float g_h2[NE];
__device__ float g_s1[NE];
__device__ float g_x[NB * KM];

// Grid barrier state (self-resetting; safe across graph replays)
__device__ unsigned g_bar_cnt;
__device__ volatile unsigned g_bar_gen;

__device__ __forceinline__ float ex2f(float x) {
    float y;
    asm("ex2.approx.ftz.f32 %0, %1;" : "=f"(y) : "f"(x));
    return y;
}

__device__ __forceinline__ uint32_t s2u(const void* p) {
    return (uint32_t)__cvta_generic_to_shared(p);
}

__device__ __forceinline__ void mbar_wait(uint32_t mbar, uint32_t parity) {
    asm volatile(
        "{\n\t"
        ".reg .pred P;\n\t"
        "WAIT_%=:\n\t"
        "mbarrier.try_wait.parity.acquire.cta.shared::cta.b64 P, [%0], %1, 0x989680;\n\t"
        "@P bra.uni DONE_%=;\n\t"
        "bra.uni WAIT_%=;\n\t"
        "DONE_%=:\n\t"
        "}"
        :: "r"(mbar), "r"(parity) : "memory");
}

// Device-wide barrier. All NCTA CTAs resident (1 CTA/SM: 187.5KB smem).
__device__ __forceinline__ void grid_barrier() {
    __threadfence();
    __syncthreads();
    if (threadIdx.x == 0) {
        unsigned my = g_bar_gen;
        if (atomicAdd(&g_bar_cnt, 1u) == NCTA - 1) {
            g_bar_cnt = 0;
            __threadfence();
            g_bar_gen = my + 1;
        } else {
            while (g_bar_gen == my) { __nanosleep(64); }
        }
    }
    __syncthreads();
}

__global__ __launch_bounds__(NTHR, 1) void kF(const float* __restrict__ emb,
                                              const float* __restrict__ W,
                                              const float* __restrict__ a,
                                              const int*   __restrict__ adj,
                                              const float* __restrict__ fw,
                                              const float* __restrict__ fb,
                                              float* __restrict__ out) {
    extern __shared__ float sx[];   // B: 5 tables (40KB) + ring (128KB); C: g_x (187.5KB)
    __shared__ unsigned long long mbF[RING];
    __shared__ unsigned long long mbE[RING];
    __shared__ float redbuf[WPB];
    __shared__ float part[WPB][8];

    int tid = threadIdx.x;
    int lane = tid & 31;
    int wid = tid >> 5;
    int gw = blockIdx.x * WPB + wid;

    // mbarrier init (fresh smem each launch; ordered before phase B by grid_barrier)
    if (tid == 0) {
#pragma unroll
        for (int s = 0; s < RING; s++) {
            uint32_t f = s2u(&mbF[s]), e = s2u(&mbE[s]);
            asm volatile("mbarrier.init.shared.b64 [%0], 1;" :: "r"(f) : "memory");
            asm volatile("mbarrier.init.shared.b64 [%0], 1;" :: "r"(e) : "memory");
        }
    }

    // ================= Phase A: h = emb@W ; s1 ; s2 =================
    if (gw < NE) {
        int r = gw;
        float e0 = __ldg(&emb[(size_t)r * 64 + lane]);
        float e1 = __ldg(&emb[(size_t)r * 64 + 32 + lane]);
        float w00 = __ldg(&W[lane * 3 + 0]), w10 = __ldg(&W[(lane + 32) * 3 + 0]);
        float w01 = __ldg(&W[lane * 3 + 1]), w11 = __ldg(&W[(lane + 32) * 3 + 1]);
        float w02 = __ldg(&W[lane * 3 + 2]), w12 = __ldg(&W[(lane + 32) * 3 + 2]);
        float h0 = fmaf(e0, w00, e1 * w10);
        float h1 = fmaf(e0, w01, e1 * w11);
        float h2 = fmaf(e0, w02, e1 * w12);
#pragma unroll
        for (int o = 16; o; o >>= 1) {
            h0 += __shfl_xor_sync(~0u, h0, o);
            h1 += __shfl_xor_sync(~0u, h1, o);
            h2 += __shfl_xor_sync(~0u, h2, o);
        }
        if (lane == 0) {
            g_h0[r] = h0; g_h1[r] = h1; g_h2[r] = h2;
            g_s1[r] = h0 * __ldg(&a[0]) + h1 * __ldg(&a[1]) + h2 * __ldg(&a[2]);
            g_s2[r] = h0 * __ldg(&a[3]) + h1 * __ldg(&a[4]) + h2 * __ldg(&a[5]);
        }
    }

    grid_barrier();

    // ================= Phase B: bulk-streamed masked softmax + aggregation =================
    float* ss1 = sx;
    float* ss2 = sx + NE;
    float* sh0 = sx + 2 * NE;
    float* sh1 = sx + 3 * NE;
    float* sh2 = sx + 4 * NE;
    char* ring = (char*)(sx + 10240);      // byte offset 40960, 16 x 8KB = 128KB

    float mx = -1e30f;
    for (int q = tid; q < NE / 4; q += NTHR) {
        float4 v2 = __ldcg(reinterpret_cast<const float4*>(g_s2) + q);
        reinterpret_cast<float4*>(ss2)[q] = v2;
        reinterpret_cast<float4*>(ss1)[q] = __ldcg(reinterpret_cast<const float4*>(g_s1) + q);
        reinterpret_cast<float4*>(sh0)[q] = __ldcg(reinterpret_cast<const float4*>(g_h0) + q);
        reinterpret_cast<float4*>(sh1)[q] = __ldcg(reinterpret_cast<const float4*>(g_h1) + q);
        reinterpret_cast<float4*>(sh2)[q] = __ldcg(reinterpret_cast<const float4*>(g_h2) + q);
        mx = fmaxf(fmaxf(fmaxf(mx, v2.x), fmaxf(v2.y, v2.z)), v2.w);
    }
#pragma unroll
    for (int o = 16; o; o >>= 1) mx = fmaxf(mx, __shfl_xor_sync(~0u, mx, o));
    if (lane == 0) redbuf[wid] = mx;
    __syncthreads();
    float s2max = redbuf[0];
#pragma unroll
    for (int w = 1; w < WPB; w++) s2max = fmaxf(s2max, redbuf[w]);

    int lo = (int)(((long long)blockIdx.x * ROWS_TOTAL) / NCTA);
    int hi = (int)(((long long)(blockIdx.x + 1) * ROWS_TOTAL) / NCTA);
    int R = hi - lo;                       // 108 or 109 contiguous 8KB rows

    uint32_t ringu = s2u(ring);
    uint32_t mbFu = s2u(&mbF[0]);
    uint32_t mbEu = s2u(&mbE[0]);

    if (wid == 31) {
        // -------- Producer: stream R contiguous 8KB rows via cp.async.bulk --------
        // Slot s = r & 15; fill index f = r >> 4; waits empty parity (f&1)^1
        // (first wait parity 1 passes immediately on a fresh barrier).
        if (lane == 0) {
            for (int r = 0; r < R; r++) {
                int s = r & (RING - 1);
                mbar_wait(mbEu + s * 8, ((r >> 4) & 1) ^ 1);
                uint32_t fb_ = mbFu + s * 8;
                asm volatile("mbarrier.arrive.expect_tx.shared.b64 _, [%0], %1;"
                             :: "r"(fb_), "r"(ROW_BYTES) : "memory");
                const int* src = adj + (size_t)(lo + r) * NE;
                uint32_t dst = ringu + s * 8192;
                asm volatile(
                    "cp.async.bulk.shared::cluster.global.mbarrier::complete_tx::bytes [%0], [%1], %2, [%3];"
                    :: "r"(dst), "l"(src), "r"(ROW_BYTES), "r"(fb_) : "memory");
            }
        }
    } else if (wid < CONS_W) {
        // -------- Consumers: warp w owns slot w (strict SPSC, no parity aliasing) --------
        for (int r = wid; r < R; r += CONS_W) {
            int s = wid;                   // == r & 15, since stride == RING
            uint32_t k = (uint32_t)(r >> 4);
            mbar_wait(mbFu + s * 8, k & 1);

            int p = lo + r;
            int b = p / NE;
            int i = p - b * NE;
            float s1i = ss1[i];
            float ts = s1i + s2max;
            float c = fmaxf(fmaxf(ts, ALPHA * ts), MASKF);
            float negc = -c * L2E;
            float w0 = ex2f(fmaf(MASKF, L2E, negc));

            const int4* arow = reinterpret_cast<const int4*>(ring + (size_t)s * 8192);
            float Z = 0.f, B0 = 0.f, B1 = 0.f, B2 = 0.f;

#pragma unroll 5
            for (int it = 0; it < 15; it++) {
                int idx = it * 32 + lane;
                int4 av = arow[idx];
                float4 s2v = reinterpret_cast<const float4*>(ss2)[idx];
                float4 h0v = reinterpret_cast<const float4*>(sh0)[idx];
                float4 h1v = reinterpret_cast<const float4*>(sh1)[idx];
                float4 h2v = reinterpret_cast<const float4*>(sh2)[idx];
#pragma unroll
                for (int cmp = 0; cmp < 4; cmp++) {
                    float t = s1i + (&s2v.x)[cmp];
                    float e = fmaxf(t, ALPHA * t);
                    float wf = ex2f(fmaf(e, L2E, negc));
                    float w = ((&av.x)[cmp] != 0) ? wf : w0;
                    Z += w;
                    B0 = fmaf(w, (&h0v.x)[cmp], B0);
                    B1 = fmaf(w, (&h1v.x)[cmp], B1);
                    B2 = fmaf(w, (&h2v.x)[cmp], B2);
                }
            }
            if (lane < 20) {               // idx 480..499 -> j 1920..1999
                int idx = 480 + lane;
                int4 av = arow[idx];
                float4 s2v = reinterpret_cast<const float4*>(ss2)[idx];
                float4 h0v = reinterpret_cast<const float4*>(sh0)[idx];
                float4 h1v = reinterpret_cast<const float4*>(sh1)[idx];
                float4 h2v = reinterpret_cast<const float4*>(sh2)[idx];
#pragma unroll
                for (int cmp = 0; cmp < 4; cmp++) {
                    float t = s1i + (&s2v.x)[cmp];
                    float e = fmaxf(t, ALPHA * t);
                    float wf = ex2f(fmaf(e, L2E, negc));
                    float w = ((&av.x)[cmp] != 0) ? wf : w0;
                    Z += w;
                    B0 = fmaf(w, (&h0v.x)[cmp], B0);
                    B1 = fmaf(w, (&h1v.x)[cmp], B1);
                    B2 = fmaf(w, (&h2v.x)[cmp], B2);
                }
            }

            __syncwarp();
            if (lane == 0) {               // slot consumed; free it for the producer
                uint32_t eb = mbEu + s * 8;
                asm volatile("mbarrier.arrive.shared.b64 _, [%0];" :: "r"(eb) : "memory");
            }

#pragma unroll
            for (int o = 16; o; o >>= 1) {
                Z  += __shfl_xor_sync(~0u, Z, o);
                B0 += __shfl_xor_sync(~0u, B0, o);
                B1 += __shfl_xor_sync(~0u, B1, o);
                B2 += __shfl_xor_sync(~0u, B2, o);
            }
            if (lane == 0) {
                float inv = 1.0f / Z;
                float p0 = B0 * inv, p1 = B1 * inv, p2 = B2 * inv;
                float x0 = (p0 > 0.f) ? p0 : expm1f(p0);
                float x1 = (p1 > 0.f) ? p1 : expm1f(p1);
                float x2 = (p2 > 0.f) ? p2 : expm1f(p2);
                float* xp = g_x + (size_t)b * KM + (size_t)i * 3;
                xp[0] = x0; xp[1] = x1; xp[2] = x2;
            }
        }
    }

    asm volatile("fence.proxy.async.shared::cta;" ::: "memory");
    grid_barrier();

    // ================= Phase C: out[b,k] = x[b,:] . fw[k,:] + fb[k] =================
    for (int q = tid; q < (NB * KM) / 4; q += NTHR)
        reinterpret_cast<float4*>(sx)[q] = __ldcg(reinterpret_cast<const float4*>(g_x) + q);
    __syncthreads();

    int cta = blockIdx.x;
    bool two = (cta < 108);
    int kstart = two ? 2 * cta : 216 + (cta - 108);
    int k = two ? (kstart + (wid >> 4)) : kstart;
    int qstart = two ? ((wid & 15) * 32 + lane) : (wid * 32 + lane);
    int qstep = two ? 512 : 1024;

    const float4* wr = reinterpret_cast<const float4*>(fw + (size_t)k * KM);

    float acc[8];
#pragma unroll
    for (int b = 0; b < 8; b++) acc[b] = 0.f;

    for (int q = qstart; q < KM / 4; q += qstep) {
        float4 wv = __ldcs(&wr[q]);
#pragma unroll
        for (int b = 0; b < 8; b++) {
            float4 xv = reinterpret_cast<const float4*>(sx)[b * (KM / 4) + q];
            acc[b] = fmaf(wv.x, xv.x, acc[b]);
            acc[b] = fmaf(wv.y, xv.y, acc[b]);
            acc[b] = fmaf(wv.z, xv.z, acc[b]);
            acc[b] = fmaf(wv.w, xv.w, acc[b]);
        }
    }

#pragma unroll
    for (int b = 0; b < 8; b++)
#pragma unroll
        for (int o = 16; o; o >>= 1)
            acc[b] += __shfl_xor_sync(~0u, acc[b], o);

    if (lane == 0) {
#pragma unroll
        for (int b = 0; b < 8; b++) part[wid][b] = acc[b];
    }
    __syncthreads();

    if (two) {
        if (tid < 16) {
            int okl = tid >> 3;
            int b = tid & 7;
            int ok = kstart + okl;
            float s = fb[ok];
#pragma unroll
            for (int w = 0; w < 16; w++) s += part[okl * 16 + w][b];
            out[(size_t)b * NHID + ok] = s;
        }
    } else {
        if (tid < 8) {
            int b = tid;
            float s = fb[kstart];
#pragma unroll
            for (int w = 0; w < WPB; w++) s += part[w][b];
            out[(size_t)b * NHID + kstart] = s;
        }
    }
}

extern "C" void kernel_launch(void* const* d_in, const int* in_sizes, int n_in,
                              void* d_out, int out_size) {
    const float* emb   = (const float*)d_in[0];
    const float* W     = (const float*)d_in[1];
    const float* a     = (const float*)d_in[2];
    const float* fc1_w = (const float*)d_in[3];
    const float* fc1_b = (const float*)d_in[4];
    const int*   adj   = (const int*)d_in[5];
    float* out = (float*)d_out;

    cudaFuncSetAttribute(kF, cudaFuncAttributeMaxDynamicSharedMemorySize,
                         NB * KM * (int)sizeof(float));

    kF<<<NCTA, NTHR, NB * KM * sizeof(float)>>>(emb, W, a, adj, fc1_w, fc1_b, out);
}

// round 17
// speedup vs baseline: 1.0393x; 1.0393x over previous
#include <cuda_runtime.h>
#include <cstdint>

#define NE 2000
#define NB 8
#define NHID 256
#define ALPHA 0.2f
#define MASKF 9e-15f
#define L2E 1.4426950408889634f
#define KM (NE * 3)          // 6000
#define NCTA 148
#define NTHR 1024
#define WPB 32
#define NWARPS (NCTA * WPB)  // 4736

// Device scratch (no allocations allowed)
__device__ float g_s2[NE];
__device__ float g_h0[NE];
__device__ float g_h1[NE];
__device__ float g_h2[NE];
__device__ float g_s1[NE];
__device__ float g_x[NB * KM];

// Grid barrier state (self-resetting; safe across graph replays)
__device__ unsigned g_bar_cnt;
__device__ volatile unsigned g_bar_gen;

__device__ __forceinline__ float ex2f(float x) {
    float y;
    asm("ex2.approx.ftz.f32 %0, %1;" : "=f"(y) : "f"(x));
    return y;
}

// L2 cache-eviction policies (createpolicy works with any load width via cache_hint)
__device__ __forceinline__ uint64_t pol_evict_last() {
    uint64_t pol;
    asm("createpolicy.fractional.L2::evict_last.b64 %0, 1.0;" : "=l"(pol));
    return pol;
}
__device__ __forceinline__ uint64_t pol_evict_first() {
    uint64_t pol;
    asm("createpolicy.fractional.L2::evict_first.b64 %0, 1.0;" : "=l"(pol));
    return pol;
}
__device__ __forceinline__ int4 ld4_pol(const int* p, uint64_t pol) {
    int4 v;
    asm("ld.global.nc.L2::cache_hint.v4.s32 {%0,%1,%2,%3}, [%4], %5;"
        : "=r"(v.x), "=r"(v.y), "=r"(v.z), "=r"(v.w) : "l"(p), "l"(pol));
    return v;
}

// Device-wide barrier. All NCTA CTAs resident (1 CTA/SM: 187.5KB smem).
__device__ __forceinline__ void grid_barrier() {
    __threadfence();
    __syncthreads();
    if (threadIdx.x == 0) {
        unsigned my = g_bar_gen;
        if (atomicAdd(&g_bar_cnt, 1u) == NCTA - 1) {
            g_bar_cnt = 0;
            __threadfence();
            g_bar_gen = my + 1;
        } else {
            while (g_bar_gen == my) { __nanosleep(64); }
        }
    }
    __syncthreads();
}

// Process 4 batch planes for row i. First NEL planes pinned (evict_last), rest streamed.
template <int NEL>
__device__ __forceinline__ void proc_quad(const int* const bp[4], int lane,
                                          uint64_t pel, uint64_t pef,
                                          const float* ss2, const float* sh0,
                                          const float* sh1, const float* sh2,
                                          float s1i, float negc, float w0,
                                          float Zb[4], float A0[4], float A1[4], float A2[4]) {
#pragma unroll 1
    for (int it = 0; it < 15; it++) {
        int j0 = it * 128 + lane * 4;
        int4 av[4];
#pragma unroll
        for (int b = 0; b < 4; b++)
            av[b] = ld4_pol(bp[b] + j0, (b < NEL) ? pel : pef);
        float4 s2v = *reinterpret_cast<const float4*>(&ss2[j0]);
        float4 h0v = *reinterpret_cast<const float4*>(&sh0[j0]);
        float4 h1v = *reinterpret_cast<const float4*>(&sh1[j0]);
        float4 h2v = *reinterpret_cast<const float4*>(&sh2[j0]);
#pragma unroll
        for (int cmp = 0; cmp < 4; cmp++) {
            float t = s1i + (&s2v.x)[cmp];
            float e = fmaxf(t, ALPHA * t);
            float wf = ex2f(fmaf(e, L2E, negc));
            float hj0 = (&h0v.x)[cmp], hj1 = (&h1v.x)[cmp], hj2 = (&h2v.x)[cmp];
#pragma unroll
            for (int b = 0; b < 4; b++) {
                float w = ((&av[b].x)[cmp] != 0) ? wf : w0;
                Zb[b] += w;
                A0[b] = fmaf(w, hj0, A0[b]);
                A1[b] = fmaf(w, hj1, A1[b]);
                A2[b] = fmaf(w, hj2, A2[b]);
            }
        }
    }
    // Epilogue: j0 in [1920, 2000) -> lanes 0..19
    if (lane < 20) {
        int j0 = 1920 + lane * 4;
        int4 av[4];
#pragma unroll
        for (int b = 0; b < 4; b++)
            av[b] = ld4_pol(bp[b] + j0, (b < NEL) ? pel : pef);
        float4 s2v = *reinterpret_cast<const float4*>(&ss2[j0]);
        float4 h0v = *reinterpret_cast<const float4*>(&sh0[j0]);
        float4 h1v = *reinterpret_cast<const float4*>(&sh1[j0]);
        float4 h2v = *reinterpret_cast<const float4*>(&sh2[j0]);
#pragma unroll
        for (int cmp = 0; cmp < 4; cmp++) {
            float t = s1i + (&s2v.x)[cmp];
            float e = fmaxf(t, ALPHA * t);
            float wf = ex2f(fmaf(e, L2E, negc));
            float hj0 = (&h0v.x)[cmp], hj1 = (&h1v.x)[cmp], hj2 = (&h2v.x)[cmp];
#pragma unroll
            for (int b = 0; b < 4; b++) {
                float w = ((&av[b].x)[cmp] != 0) ? wf : w0;
                Zb[b] += w;
                A0[b] = fmaf(w, hj0, A0[b]);
                A1[b] = fmaf(w, hj1, A1[b]);
                A2[b] = fmaf(w, hj2, A2[b]);
            }
        }
    }
}

__global__ __launch_bounds__(NTHR, 1) void kF(const float* __restrict__ emb,
                                              const float* __restrict__ W,
                                              const float* __restrict__ a,
                                              const int*   __restrict__ adj,
                                              const float* __restrict__ fw,
                                              const float* __restrict__ fb,
                                              float* __restrict__ out) {
    extern __shared__ float sx[];          // phase B: 4 tables of 2000; phase C: g_x [8][6000]
    __shared__ float redbuf[WPB];
    __shared__ float part[WPB][8];

    int tid = threadIdx.x;
    int lane = tid & 31;
    int wid = tid >> 5;
    int gw = blockIdx.x * WPB + wid;       // global warp id 0..4735

    // ================= Phase A: h = emb@W ; s1 ; s2 =================
    if (gw < NE) {
        int r = gw;
        float e0 = __ldg(&emb[(size_t)r * 64 + lane]);
        float e1 = __ldg(&emb[(size_t)r * 64 + 32 + lane]);
        float w00 = __ldg(&W[lane * 3 + 0]), w10 = __ldg(&W[(lane + 32) * 3 + 0]);
        float w01 = __ldg(&W[lane * 3 + 1]), w11 = __ldg(&W[(lane + 32) * 3 + 1]);
        float w02 = __ldg(&W[lane * 3 + 2]), w12 = __ldg(&W[(lane + 32) * 3 + 2]);
        float h0 = fmaf(e0, w00, e1 * w10);
        float h1 = fmaf(e0, w01, e1 * w11);
        float h2 = fmaf(e0, w02, e1 * w12);
#pragma unroll
        for (int o = 16; o; o >>= 1) {
            h0 += __shfl_xor_sync(~0u, h0, o);
            h1 += __shfl_xor_sync(~0u, h1, o);
            h2 += __shfl_xor_sync(~0u, h2, o);
        }
        if (lane == 0) {
            g_h0[r] = h0; g_h1[r] = h1; g_h2[r] = h2;
            g_s1[r] = h0 * __ldg(&a[0]) + h1 * __ldg(&a[1]) + h2 * __ldg(&a[2]);
            g_s2[r] = h0 * __ldg(&a[3]) + h1 * __ldg(&a[4]) + h2 * __ldg(&a[5]);
        }
    }

    grid_barrier();

    // ================= Phase B: masked softmax + aggregation + ELU =================
    // One warp per (row i, batch-half): 4000 tasks over 4736 warps, one round.
    float* ss2 = sx;
    float* sh0 = sx + NE;
    float* sh1 = sx + 2 * NE;
    float* sh2 = sx + 3 * NE;

    float mx = -1e30f;
    for (int q = tid; q < NE / 4; q += NTHR) {
        float4 v2 = __ldcg(reinterpret_cast<const float4*>(g_s2) + q);
        reinterpret_cast<float4*>(ss2)[q] = v2;
        reinterpret_cast<float4*>(sh0)[q] = __ldcg(reinterpret_cast<const float4*>(g_h0) + q);
        reinterpret_cast<float4*>(sh1)[q] = __ldcg(reinterpret_cast<const float4*>(g_h1) + q);
        reinterpret_cast<float4*>(sh2)[q] = __ldcg(reinterpret_cast<const float4*>(g_h2) + q);
        mx = fmaxf(fmaxf(fmaxf(mx, v2.x), fmaxf(v2.y, v2.z)), v2.w);
    }
#pragma unroll
    for (int o = 16; o; o >>= 1) mx = fmaxf(mx, __shfl_xor_sync(~0u, mx, o));
    if (lane == 0) redbuf[wid] = mx;
    __syncthreads();
    float s2max = redbuf[0];
#pragma unroll
    for (int w = 1; w < WPB; w++) s2max = fmaxf(s2max, redbuf[w]);

    if (gw < 2 * NE) {
        int i  = gw >> 1;                  // row
        int b0 = (gw & 1) * 4;             // batch half: 0..3 or 4..7
        float s1i = __ldcg(&g_s1[i]);
        float ts = s1i + s2max;
        float c = fmaxf(fmaxf(ts, ALPHA * ts), MASKF);   // valid softmax shift
        float negc = -c * L2E;
        float w0 = ex2f(fmaf(MASKF, L2E, negc));         // weight of masked entries

        uint64_t pel = pol_evict_last();
        uint64_t pef = pol_evict_first();

        const int* bp[4];
#pragma unroll
        for (int b = 0; b < 4; b++)
            bp[b] = adj + (size_t)(b0 + b) * NE * NE + (size_t)i * NE;

        float Zb[4], A0[4], A1[4], A2[4];
#pragma unroll
        for (int b = 0; b < 4; b++) { Zb[b] = 0.f; A0[b] = 0.f; A1[b] = 0.f; A2[b] = 0.f; }

        // Batches 0..6 pinned in L2 (evict_last, 112MB); batch 7 streamed (16MB).
        if (b0 == 0)
            proc_quad<4>(bp, lane, pel, pef, ss2, sh0, sh1, sh2, s1i, negc, w0, Zb, A0, A1, A2);
        else
            proc_quad<3>(bp, lane, pel, pef, ss2, sh0, sh1, sh2, s1i, negc, w0, Zb, A0, A1, A2);

        // warp reductions (16 accumulators)
#pragma unroll
        for (int b = 0; b < 4; b++) {
#pragma unroll
            for (int o = 16; o; o >>= 1) {
                Zb[b] += __shfl_xor_sync(~0u, Zb[b], o);
                A0[b] += __shfl_xor_sync(~0u, A0[b], o);
                A1[b] += __shfl_xor_sync(~0u, A1[b], o);
                A2[b] += __shfl_xor_sync(~0u, A2[b], o);
            }
        }

        if (lane == 0) {
#pragma unroll
            for (int b = 0; b < 4; b++) {
                float inv = 1.0f / Zb[b];
                float p0 = A0[b] * inv;
                float p1 = A1[b] * inv;
                float p2 = A2[b] * inv;
                float x0 = (p0 > 0.f) ? p0 : expm1f(p0);
                float x1 = (p1 > 0.f) ? p1 : expm1f(p1);
                float x2 = (p2 > 0.f) ? p2 : expm1f(p2);
                float* xp = g_x + (size_t)(b0 + b) * KM + (size_t)i * 3;
                xp[0] = x0; xp[1] = x1; xp[2] = x2;
            }
        }
    }

    grid_barrier();

    // ================= Phase C: out[b,k] = x[b,:] . fw[k,:] + fb[k] =================
    // Stage full g_x (187.5KB) into smem; fw (6.1MB) persists in L2 via default policy.
    for (int q = tid; q < (NB * KM) / 4; q += NTHR)
        reinterpret_cast<float4*>(sx)[q] = __ldcg(reinterpret_cast<const float4*>(g_x) + q);
    __syncthreads();

    int cta = blockIdx.x;
    bool two = (cta < 108);
    int kstart = two ? 2 * cta : 216 + (cta - 108);
    int k = two ? (kstart + (wid >> 4)) : kstart;
    int qstart = two ? ((wid & 15) * 32 + lane) : (wid * 32 + lane);
    int qstep = two ? 512 : 1024;

    const float4* wr = reinterpret_cast<const float4*>(fw + (size_t)k * KM);

    float acc[8];
#pragma unroll
    for (int b = 0; b < 8; b++) acc[b] = 0.f;

    for (int q = qstart; q < KM / 4; q += qstep) {
        float4 wv = __ldg(&wr[q]);
#pragma unroll
        for (int b = 0; b < 8; b++) {
            float4 xv = reinterpret_cast<const float4*>(sx)[b * (KM / 4) + q];
            acc[b] = fmaf(wv.x, xv.x, acc[b]);
            acc[b] = fmaf(wv.y, xv.y, acc[b]);
            acc[b] = fmaf(wv.z, xv.z, acc[b]);
            acc[b] = fmaf(wv.w, xv.w, acc[b]);
        }
    }

#pragma unroll
    for (int b = 0; b < 8; b++)
#pragma unroll
        for (int o = 16; o; o >>= 1)
            acc[b] += __shfl_xor_sync(~0u, acc[b], o);

    if (lane == 0) {
#pragma unroll
        for (int b = 0; b < 8; b++) part[wid][b] = acc[b];
    }
    __syncthreads();

    if (two) {
        if (tid < 16) {
            int okl = tid >> 3;
            int b = tid & 7;
            int ok = kstart + okl;
            float s = fb[ok];
#pragma unroll
            for (int w = 0; w < 16; w++) s += part[okl * 16 + w][b];
            out[(size_t)b * NHID + ok] = s;
        }
    } else {
        if (tid < 8) {
            int b = tid;
            float s = fb[kstart];
#pragma unroll
            for (int w = 0; w < WPB; w++) s += part[w][b];
            out[(size_t)b * NHID + kstart] = s;
        }
    }
}

extern "C" void kernel_launch(void* const* d_in, const int* in_sizes, int n_in,
                              void* d_out, int out_size) {
    const float* emb   = (const float*)d_in[0];
    const float* W     = (const float*)d_in[1];
    const float* a     = (const float*)d_in[2];
    const float* fc1_w = (const float*)d_in[3];
    const float* fc1_b = (const float*)d_in[4];
    const int*   adj   = (const int*)d_in[5];
    float* out = (float*)d_out;

    cudaFuncSetAttribute(kF, cudaFuncAttributeMaxDynamicSharedMemorySize,
                         NB * KM * (int)sizeof(float));

    kF<<<NCTA, NTHR, NB * KM * sizeof(float)>>>(emb, W, a, adj, fc1_w, fc1_b, out);
}